// round 1
// baseline (speedup 1.0000x reference)
#include <cuda_runtime.h>
#include <cstdint>
#include <cstddef>

// ---------------------------------------------------------------------------
// FGAEmbedder fused pipeline, GB300 sm_103a
// Round 1: TF32 mma.sync GEMMs + algebraic collapse of the TxT pairwise term.
//
//   pw_pot[b,t] = mean_s( xn[b,t]·yn[b,s] ) = xn[b,t] · mean_s(yn[b,s])
//
// Launch sequence (all on default stream, graph-capturable, alloc-free):
//   1. H  = relu(x @ fc1_w^T + fc1_b)         gemm_tf32<true>
//   2. U  = H @ fc2_w^T + fc2_b               gemm_tf32<false>
//   3. E  = relu(U @ un_emb_w^T + un_emb_b)   gemm_tf32<true>
//   4. XE = U @ pw_x_w^T + pw_x_b             gemm_tf32<false>
//   5. YE = U @ pw_y_w^T + pw_y_b             gemm_tf32<false>
//   6. rowops: un_pot, 1/||xe||, YE <- yn (in place)
//   7. ybar[b] = mean_t yn[b,t]
//   8. scores[b,t] = rw0*un_pot + rw1*(xe·ybar)/||xe||
//   9. softmax over T, out[b,:] = sum_t w_t * U[b,t,:]
// ---------------------------------------------------------------------------

namespace {
constexpr int Bn = 32, Tn = 1024, INn = 1536, Dn = 768;
constexpr int Mn = Bn * Tn;  // 32768
}

// Scratch (static __device__ globals: allocation-free rule)
__device__ float g_H [(size_t)Mn * INn];  // 192 MB
__device__ float g_U [(size_t)Mn * Dn];   //  96 MB
__device__ float g_E [(size_t)Mn * Dn];
__device__ float g_XE[(size_t)Mn * Dn];
__device__ float g_YE[(size_t)Mn * Dn];   // becomes yn in-place
__device__ float g_YB[Bn * Dn];
__device__ float g_UP[Mn];
__device__ float g_INX[Mn];
__device__ float g_SC[Mn];

// ---------------------------------------------------------------------------
// helpers
// ---------------------------------------------------------------------------
__device__ __forceinline__ void cp16(float* s, const float* g) {
    uint32_t sa = (uint32_t)__cvta_generic_to_shared(s);
    asm volatile("cp.async.cg.shared.global [%0], [%1], 16;\n" :: "r"(sa), "l"(g));
}
__device__ __forceinline__ void cp_commit() {
    asm volatile("cp.async.commit_group;\n");
}
template <int NW>
__device__ __forceinline__ void cp_wait() {
    asm volatile("cp.async.wait_group %0;\n" :: "n"(NW));
}
__device__ __forceinline__ uint32_t f2tf(float x) {
    uint32_t r;
    asm("cvt.rna.tf32.f32 %0, %1;\n" : "=r"(r) : "f"(x));
    return r;
}
__device__ __forceinline__ void mma8(float* c, const uint32_t* a, const uint32_t* b) {
    asm volatile(
        "mma.sync.aligned.m16n8k8.row.col.f32.tf32.tf32.f32 "
        "{%0,%1,%2,%3}, {%4,%5,%6,%7}, {%8,%9}, {%0,%1,%2,%3};\n"
        : "+f"(c[0]), "+f"(c[1]), "+f"(c[2]), "+f"(c[3])
        : "r"(a[0]), "r"(a[1]), "r"(a[2]), "r"(a[3]), "r"(b[0]), "r"(b[1]));
}
// smem tile [128 rows][32 floats], float4-granular XOR swizzle -> conflict-free
// both for cp.async stores and mma fragment LDS.
__device__ __forceinline__ int swz(int r, int c) {
    return r * 32 + (((((c >> 2) ^ (r & 7))) << 2) | (c & 3));
}

// ---------------------------------------------------------------------------
// GEMM: C[M,N] = A[M,K] @ W[N,K]^T + bias[N]  (optional relu)
// Tiles: CTA 128x128x32, warps 2(m)x4(n) -> warp tile 64x32, m16n8k8 tf32.
// Requires: M%128==0, N%128==0, K%32==0 (holds for all shapes here).
// Dynamic smem: 64 KB (double-buffered A+B tiles).
// ---------------------------------------------------------------------------
template <bool RELU>
__global__ __launch_bounds__(256, 2) void gemm_tf32(
    const float* __restrict__ A, const float* __restrict__ W,
    const float* __restrict__ bias, float* __restrict__ C,
    int N, int K)
{
    extern __shared__ float smem[];  // [0,8192): A stages, [8192,16384): B stages
    const int tid  = threadIdx.x;
    const int lane = tid & 31, wrp = tid >> 5;
    const int wm = wrp >> 2, wn = wrp & 3;   // 2 x 4 warp grid
    const int g = lane >> 2, t = lane & 3;
    const int m0 = blockIdx.y * 128, n0 = blockIdx.x * 128;

    // global->shared loader mapping (per thread: 4 x 16B for A, 4 for B)
    const int c4 = tid & 7, rb = tid >> 3;        // rb 0..31
    const int sc4 = c4 ^ (rb & 7);
    const int soff = rb * 32 + sc4 * 4;
    const float* gA = A + (size_t)(m0 + rb) * K + c4 * 4;
    const float* gW = W + (size_t)(n0 + rb) * K + c4 * 4;

    float acc[4][4][4];
    #pragma unroll
    for (int i = 0; i < 4; i++)
        #pragma unroll
        for (int j = 0; j < 4; j++)
            #pragma unroll
            for (int q = 0; q < 4; q++) acc[i][j][q] = 0.f;

    const int kiters = K >> 5;

    // prologue: stage 0
    #pragma unroll
    for (int p = 0; p < 4; p++) {
        cp16(&smem[soff + p * 1024],        gA + (size_t)p * 32 * K);
        cp16(&smem[8192 + soff + p * 1024], gW + (size_t)p * 32 * K);
    }
    cp_commit();

    for (int it = 0; it < kiters; ++it) {
        const int st = it & 1;
        if (it + 1 < kiters) {
            const int k0  = (it + 1) << 5;
            const int stn = (it + 1) & 1;
            #pragma unroll
            for (int p = 0; p < 4; p++) {
                cp16(&smem[stn * 4096 + soff + p * 1024],        gA + k0 + (size_t)p * 32 * K);
                cp16(&smem[8192 + stn * 4096 + soff + p * 1024], gW + k0 + (size_t)p * 32 * K);
            }
            cp_commit();
            cp_wait<1>();
        } else {
            cp_wait<0>();
        }
        __syncthreads();

        const float* sA = smem + st * 4096;
        const float* sB = smem + 8192 + st * 4096;

        #pragma unroll
        for (int kk4 = 0; kk4 < 8; kk4 += 2) {   // kk = kk4*4 in {0,8,16,24}
            uint32_t af[4][4], bf[4][2];
            #pragma unroll
            for (int mf = 0; mf < 4; mf++) {
                const int r1 = wm * 64 + mf * 16 + g;
                af[mf][0] = f2tf(sA[swz(r1,     kk4 * 4 + t)]);
                af[mf][1] = f2tf(sA[swz(r1 + 8, kk4 * 4 + t)]);
                af[mf][2] = f2tf(sA[swz(r1,     kk4 * 4 + 4 + t)]);
                af[mf][3] = f2tf(sA[swz(r1 + 8, kk4 * 4 + 4 + t)]);
            }
            #pragma unroll
            for (int nf = 0; nf < 4; nf++) {
                const int rn = wn * 32 + nf * 8 + g;
                bf[nf][0] = f2tf(sB[swz(rn, kk4 * 4 + t)]);
                bf[nf][1] = f2tf(sB[swz(rn, kk4 * 4 + 4 + t)]);
            }
            #pragma unroll
            for (int mf = 0; mf < 4; mf++)
                #pragma unroll
                for (int nf = 0; nf < 4; nf++)
                    mma8(acc[mf][nf], af[mf], bf[nf]);
        }
        __syncthreads();
    }

    // epilogue: bias (+relu), float2 stores
    #pragma unroll
    for (int mf = 0; mf < 4; mf++) {
        const int row = m0 + wm * 64 + mf * 16 + g;
        #pragma unroll
        for (int nf = 0; nf < 4; nf++) {
            const int col = n0 + wn * 32 + nf * 8 + 2 * t;
            const float b0 = bias[col], b1 = bias[col + 1];
            float v0 = acc[mf][nf][0] + b0;
            float v1 = acc[mf][nf][1] + b1;
            float v2 = acc[mf][nf][2] + b0;
            float v3 = acc[mf][nf][3] + b1;
            if (RELU) {
                v0 = fmaxf(v0, 0.f); v1 = fmaxf(v1, 0.f);
                v2 = fmaxf(v2, 0.f); v3 = fmaxf(v3, 0.f);
            }
            *(float2*)(C + (size_t)row       * N + col) = make_float2(v0, v1);
            *(float2*)(C + (size_t)(row + 8) * N + col) = make_float2(v2, v3);
        }
    }
}

// ---------------------------------------------------------------------------
// rowops: per row r of 32768: un_pot = e·un_red_w + b, 1/||xe||, YE <- yn
// ---------------------------------------------------------------------------
__global__ void rowops_k(const float* __restrict__ E, const float* __restrict__ XE,
                         float* __restrict__ YE,
                         const float* __restrict__ unw, const float* __restrict__ unb,
                         float* __restrict__ unpot, float* __restrict__ invnx)
{
    __shared__ float red[3][8];
    __shared__ float fin[3];
    const int r = blockIdx.x, tid = threadIdx.x;
    const size_t base = (size_t)r * 768;

    const int i0 = tid, i1 = tid + 256, i2 = tid + 512;
    const float e0 = E[base + i0], e1 = E[base + i1], e2 = E[base + i2];
    float de = e0 * unw[i0] + e1 * unw[i1] + e2 * unw[i2];
    const float x0 = XE[base + i0], x1 = XE[base + i1], x2 = XE[base + i2];
    float sx = x0 * x0 + x1 * x1 + x2 * x2;
    const float y0 = YE[base + i0], y1 = YE[base + i1], y2 = YE[base + i2];
    float sy = y0 * y0 + y1 * y1 + y2 * y2;

    #pragma unroll
    for (int o = 16; o; o >>= 1) {
        de += __shfl_xor_sync(0xffffffffu, de, o);
        sx += __shfl_xor_sync(0xffffffffu, sx, o);
        sy += __shfl_xor_sync(0xffffffffu, sy, o);
    }
    if ((tid & 31) == 0) { int w = tid >> 5; red[0][w] = de; red[1][w] = sx; red[2][w] = sy; }
    __syncthreads();
    if (tid == 0) {
        float a = 0.f, b2 = 0.f, c = 0.f;
        #pragma unroll
        for (int i = 0; i < 8; i++) { a += red[0][i]; b2 += red[1][i]; c += red[2][i]; }
        fin[2] = c;
        unpot[r] = a + unb[0];
        invnx[r] = 1.f / fmaxf(sqrtf(b2), 1e-12f);
    }
    __syncthreads();
    const float inv_ny = 1.f / fmaxf(sqrtf(fin[2]), 1e-12f);
    YE[base + i0] = y0 * inv_ny;
    YE[base + i1] = y1 * inv_ny;
    YE[base + i2] = y2 * inv_ny;
}

// ybar[b,d] = mean_t yn[b,t,d]     grid (32, 6) x 128
__global__ void ybar_k(const float* __restrict__ YN, float* __restrict__ YB)
{
    const int b = blockIdx.x, col = blockIdx.y * 128 + threadIdx.x;
    const float* p = YN + (size_t)b * 1024 * 768 + col;
    float s = 0.f;
    #pragma unroll 8
    for (int tt = 0; tt < 1024; ++tt) s += p[(size_t)tt * 768];
    YB[b * 768 + col] = s * (1.0f / 1024.0f);
}

// scores[b,t] = rw0*un_pot + rw1*(xe·ybar)/||xe||
__global__ void scores_k(const float* __restrict__ XE, const float* __restrict__ YB,
                         const float* __restrict__ invnx, const float* __restrict__ unpot,
                         const float* __restrict__ redw, float* __restrict__ sc)
{
    __shared__ float red[8];
    const int r = blockIdx.x, tid = threadIdx.x;
    const int b = r >> 10;
    const size_t base = (size_t)r * 768;
    const float* yb = YB + b * 768;
    float d = XE[base + tid] * yb[tid]
            + XE[base + tid + 256] * yb[tid + 256]
            + XE[base + tid + 512] * yb[tid + 512];
    #pragma unroll
    for (int o = 16; o; o >>= 1) d += __shfl_xor_sync(0xffffffffu, d, o);
    if ((tid & 31) == 0) red[tid >> 5] = d;
    __syncthreads();
    if (tid == 0) {
        float D = 0.f;
        #pragma unroll
        for (int i = 0; i < 8; i++) D += red[i];
        const float pw = D * invnx[r];
        sc[r] = redw[0] * unpot[r] + redw[1] * pw;
    }
}

// softmax over T + weighted sum of U rows.  grid 32 x 256
__global__ void final_k(const float* __restrict__ U, const float* __restrict__ sc,
                        float* __restrict__ out)
{
    __shared__ float wsh[1024];
    __shared__ float red[8];
    __shared__ float finv;
    const int b = blockIdx.x, tid = threadIdx.x;

    float l0 = sc[b * 1024 + tid];
    float l1 = sc[b * 1024 + tid + 256];
    float l2 = sc[b * 1024 + tid + 512];
    float l3 = sc[b * 1024 + tid + 768];
    float mx = fmaxf(fmaxf(l0, l1), fmaxf(l2, l3));
    #pragma unroll
    for (int o = 16; o; o >>= 1) mx = fmaxf(mx, __shfl_xor_sync(0xffffffffu, mx, o));
    if ((tid & 31) == 0) red[tid >> 5] = mx;
    __syncthreads();
    if (tid == 0) {
        float M = red[0];
        #pragma unroll
        for (int i = 1; i < 8; i++) M = fmaxf(M, red[i]);
        finv = M;  // temporarily hold the max
    }
    __syncthreads();
    const float M = finv;
    __syncthreads();

    l0 = expf(l0 - M); l1 = expf(l1 - M); l2 = expf(l2 - M); l3 = expf(l3 - M);
    float s = l0 + l1 + l2 + l3;
    #pragma unroll
    for (int o = 16; o; o >>= 1) s += __shfl_xor_sync(0xffffffffu, s, o);
    if ((tid & 31) == 0) red[tid >> 5] = s;
    __syncthreads();
    if (tid == 0) {
        float S = 0.f;
        #pragma unroll
        for (int i = 0; i < 8; i++) S += red[i];
        finv = 1.f / S;
    }
    __syncthreads();
    const float inv = finv;
    wsh[tid]       = l0 * inv;
    wsh[tid + 256] = l1 * inv;
    wsh[tid + 512] = l2 * inv;
    wsh[tid + 768] = l3 * inv;
    __syncthreads();

    const float* Ub = U + (size_t)b * 1024 * 768;
    float a0 = 0.f, a1 = 0.f, a2 = 0.f;
    #pragma unroll 4
    for (int tt = 0; tt < 1024; ++tt) {
        const float wt = wsh[tt];
        const float* row = Ub + (size_t)tt * 768;
        a0 += wt * row[tid];
        a1 += wt * row[tid + 256];
        a2 += wt * row[tid + 512];
    }
    out[b * 768 + tid]       = a0;
    out[b * 768 + tid + 256] = a1;
    out[b * 768 + tid + 512] = a2;
}

// ---------------------------------------------------------------------------
extern "C" void kernel_launch(void* const* d_in, const int* in_sizes, int n_in,
                              void* d_out, int out_size)
{
    (void)in_sizes; (void)n_in; (void)out_size;
    const float* x       = (const float*)d_in[0];
    const float* fc1_w   = (const float*)d_in[1];
    const float* fc1_b   = (const float*)d_in[2];
    const float* fc2_w   = (const float*)d_in[3];
    const float* fc2_b   = (const float*)d_in[4];
    const float* un_emb_w= (const float*)d_in[5];
    const float* un_emb_b= (const float*)d_in[6];
    const float* un_red_w= (const float*)d_in[7];
    const float* un_red_b= (const float*)d_in[8];
    const float* pw_x_w  = (const float*)d_in[9];
    const float* pw_x_b  = (const float*)d_in[10];
    const float* pw_y_w  = (const float*)d_in[11];
    const float* pw_y_b  = (const float*)d_in[12];
    const float* red_w   = (const float*)d_in[13];
    float* out = (float*)d_out;

    float *H, *U, *E, *XE, *YE, *YB, *UP, *INX, *SC;
    cudaGetSymbolAddress((void**)&H,   g_H);
    cudaGetSymbolAddress((void**)&U,   g_U);
    cudaGetSymbolAddress((void**)&E,   g_E);
    cudaGetSymbolAddress((void**)&XE,  g_XE);
    cudaGetSymbolAddress((void**)&YE,  g_YE);
    cudaGetSymbolAddress((void**)&YB,  g_YB);
    cudaGetSymbolAddress((void**)&UP,  g_UP);
    cudaGetSymbolAddress((void**)&INX, g_INX);
    cudaGetSymbolAddress((void**)&SC,  g_SC);

    const int smem = 64 * 1024;
    cudaFuncSetAttribute(gemm_tf32<true>,  cudaFuncAttributeMaxDynamicSharedMemorySize, smem);
    cudaFuncSetAttribute(gemm_tf32<false>, cudaFuncAttributeMaxDynamicSharedMemorySize, smem);

    // 1. H = relu(x @ fc1_w^T + fc1_b)   [32768 x 1536], K=1536
    gemm_tf32<true><<<dim3(12, 256), 256, smem>>>(x, fc1_w, fc1_b, H, 1536, 1536);
    // 2. U = H @ fc2_w^T + fc2_b         [32768 x 768], K=1536
    gemm_tf32<false><<<dim3(6, 256), 256, smem>>>(H, fc2_w, fc2_b, U, 768, 1536);
    // 3-5. E / XE / YE                   [32768 x 768], K=768
    gemm_tf32<true><<<dim3(6, 256), 256, smem>>>(U, un_emb_w, un_emb_b, E, 768, 768);
    gemm_tf32<false><<<dim3(6, 256), 256, smem>>>(U, pw_x_w, pw_x_b, XE, 768, 768);
    gemm_tf32<false><<<dim3(6, 256), 256, smem>>>(U, pw_y_w, pw_y_b, YE, 768, 768);
    // 6. row reductions + in-place normalize YE -> yn
    rowops_k<<<Mn, 256>>>(E, XE, YE, un_red_w, un_red_b, UP, INX);
    // 7. ybar = mean_t yn
    ybar_k<<<dim3(Bn, 6), 128>>>(YE, YB);
    // 8. scores
    scores_k<<<Mn, 256>>>(XE, YB, INX, UP, red_w, SC);
    // 9. softmax + weighted sum
    final_k<<<Bn, 256>>>(U, SC, out);
}

// round 3
// speedup vs baseline: 1.0024x; 1.0024x over previous
#include <cuda_runtime.h>
#include <cstdint>
#include <cstddef>

// ---------------------------------------------------------------------------
// FGAEmbedder fused pipeline, GB300 sm_103a
// Round 1: TF32 mma.sync GEMMs + algebraic collapse of the TxT pairwise term.
//
//   pw_pot[b,t] = mean_s( xn[b,t]·yn[b,s] ) = xn[b,t] · mean_s(yn[b,s])
//
// Launch sequence (all on default stream, graph-capturable, alloc-free):
//   1. H  = relu(x @ fc1_w^T + fc1_b)         gemm_tf32<true>
//   2. U  = H @ fc2_w^T + fc2_b               gemm_tf32<false>
//   3. E  = relu(U @ un_emb_w^T + un_emb_b)   gemm_tf32<true>
//   4. XE = U @ pw_x_w^T + pw_x_b             gemm_tf32<false>
//   5. YE = U @ pw_y_w^T + pw_y_b             gemm_tf32<false>
//   6. rowops: un_pot, 1/||xe||, YE <- yn (in place)
//   7. ybar[b] = mean_t yn[b,t]
//   8. scores[b,t] = rw0*un_pot + rw1*(xe·ybar)/||xe||
//   9. softmax over T, out[b,:] = sum_t w_t * U[b,t,:]
// ---------------------------------------------------------------------------

namespace {
constexpr int Bn = 32, Tn = 1024, INn = 1536, Dn = 768;
constexpr int Mn = Bn * Tn;  // 32768
}

// Scratch (static __device__ globals: allocation-free rule)
__device__ float g_H [(size_t)Mn * INn];  // 192 MB
__device__ float g_U [(size_t)Mn * Dn];   //  96 MB
__device__ float g_E [(size_t)Mn * Dn];
__device__ float g_XE[(size_t)Mn * Dn];
__device__ float g_YE[(size_t)Mn * Dn];   // becomes yn in-place
__device__ float g_YB[Bn * Dn];
__device__ float g_UP[Mn];
__device__ float g_INX[Mn];
__device__ float g_SC[Mn];

// ---------------------------------------------------------------------------
// helpers
// ---------------------------------------------------------------------------
__device__ __forceinline__ void cp16(float* s, const float* g) {
    uint32_t sa = (uint32_t)__cvta_generic_to_shared(s);
    asm volatile("cp.async.cg.shared.global [%0], [%1], 16;\n" :: "r"(sa), "l"(g));
}
__device__ __forceinline__ void cp_commit() {
    asm volatile("cp.async.commit_group;\n");
}
template <int NW>
__device__ __forceinline__ void cp_wait() {
    asm volatile("cp.async.wait_group %0;\n" :: "n"(NW));
}
__device__ __forceinline__ uint32_t f2tf(float x) {
    uint32_t r;
    asm("cvt.rna.tf32.f32 %0, %1;\n" : "=r"(r) : "f"(x));
    return r;
}
__device__ __forceinline__ void mma8(float* c, const uint32_t* a, const uint32_t* b) {
    asm volatile(
        "mma.sync.aligned.m16n8k8.row.col.f32.tf32.tf32.f32 "
        "{%0,%1,%2,%3}, {%4,%5,%6,%7}, {%8,%9}, {%0,%1,%2,%3};\n"
        : "+f"(c[0]), "+f"(c[1]), "+f"(c[2]), "+f"(c[3])
        : "r"(a[0]), "r"(a[1]), "r"(a[2]), "r"(a[3]), "r"(b[0]), "r"(b[1]));
}
// smem tile [128 rows][32 floats], float4-granular XOR swizzle -> conflict-free
// both for cp.async stores and mma fragment LDS.
__device__ __forceinline__ int swz(int r, int c) {
    return r * 32 + (((((c >> 2) ^ (r & 7))) << 2) | (c & 3));
}

// ---------------------------------------------------------------------------
// GEMM: C[M,N] = A[M,K] @ W[N,K]^T + bias[N]  (optional relu)
// Tiles: CTA 128x128x32, warps 2(m)x4(n) -> warp tile 64x32, m16n8k8 tf32.
// Requires: M%128==0, N%128==0, K%32==0 (holds for all shapes here).
// Dynamic smem: 64 KB (double-buffered A+B tiles).
// ---------------------------------------------------------------------------
template <bool RELU>
__global__ __launch_bounds__(256, 2) void gemm_tf32(
    const float* __restrict__ A, const float* __restrict__ W,
    const float* __restrict__ bias, float* __restrict__ C,
    int N, int K)
{
    extern __shared__ float smem[];  // [0,8192): A stages, [8192,16384): B stages
    const int tid  = threadIdx.x;
    const int lane = tid & 31, wrp = tid >> 5;
    const int wm = wrp >> 2, wn = wrp & 3;   // 2 x 4 warp grid
    const int g = lane >> 2, t = lane & 3;
    const int m0 = blockIdx.y * 128, n0 = blockIdx.x * 128;

    // global->shared loader mapping (per thread: 4 x 16B for A, 4 for B)
    const int c4 = tid & 7, rb = tid >> 3;        // rb 0..31
    const int sc4 = c4 ^ (rb & 7);
    const int soff = rb * 32 + sc4 * 4;
    const float* gA = A + (size_t)(m0 + rb) * K + c4 * 4;
    const float* gW = W + (size_t)(n0 + rb) * K + c4 * 4;

    float acc[4][4][4];
    #pragma unroll
    for (int i = 0; i < 4; i++)
        #pragma unroll
        for (int j = 0; j < 4; j++)
            #pragma unroll
            for (int q = 0; q < 4; q++) acc[i][j][q] = 0.f;

    const int kiters = K >> 5;

    // prologue: stage 0
    #pragma unroll
    for (int p = 0; p < 4; p++) {
        cp16(&smem[soff + p * 1024],        gA + (size_t)p * 32 * K);
        cp16(&smem[8192 + soff + p * 1024], gW + (size_t)p * 32 * K);
    }
    cp_commit();

    for (int it = 0; it < kiters; ++it) {
        const int st = it & 1;
        if (it + 1 < kiters) {
            const int k0  = (it + 1) << 5;
            const int stn = (it + 1) & 1;
            #pragma unroll
            for (int p = 0; p < 4; p++) {
                cp16(&smem[stn * 4096 + soff + p * 1024],        gA + k0 + (size_t)p * 32 * K);
                cp16(&smem[8192 + stn * 4096 + soff + p * 1024], gW + k0 + (size_t)p * 32 * K);
            }
            cp_commit();
            cp_wait<1>();
        } else {
            cp_wait<0>();
        }
        __syncthreads();

        const float* sA = smem + st * 4096;
        const float* sB = smem + 8192 + st * 4096;

        #pragma unroll
        for (int kk4 = 0; kk4 < 8; kk4 += 2) {   // kk = kk4*4 in {0,8,16,24}
            uint32_t af[4][4], bf[4][2];
            #pragma unroll
            for (int mf = 0; mf < 4; mf++) {
                const int r1 = wm * 64 + mf * 16 + g;
                af[mf][0] = f2tf(sA[swz(r1,     kk4 * 4 + t)]);
                af[mf][1] = f2tf(sA[swz(r1 + 8, kk4 * 4 + t)]);
                af[mf][2] = f2tf(sA[swz(r1,     kk4 * 4 + 4 + t)]);
                af[mf][3] = f2tf(sA[swz(r1 + 8, kk4 * 4 + 4 + t)]);
            }
            #pragma unroll
            for (int nf = 0; nf < 4; nf++) {
                const int rn = wn * 32 + nf * 8 + g;
                bf[nf][0] = f2tf(sB[swz(rn, kk4 * 4 + t)]);
                bf[nf][1] = f2tf(sB[swz(rn, kk4 * 4 + 4 + t)]);
            }
            #pragma unroll
            for (int mf = 0; mf < 4; mf++)
                #pragma unroll
                for (int nf = 0; nf < 4; nf++)
                    mma8(acc[mf][nf], af[mf], bf[nf]);
        }
        __syncthreads();
    }

    // epilogue: bias (+relu), float2 stores
    #pragma unroll
    for (int mf = 0; mf < 4; mf++) {
        const int row = m0 + wm * 64 + mf * 16 + g;
        #pragma unroll
        for (int nf = 0; nf < 4; nf++) {
            const int col = n0 + wn * 32 + nf * 8 + 2 * t;
            const float b0 = bias[col], b1 = bias[col + 1];
            float v0 = acc[mf][nf][0] + b0;
            float v1 = acc[mf][nf][1] + b1;
            float v2 = acc[mf][nf][2] + b0;
            float v3 = acc[mf][nf][3] + b1;
            if (RELU) {
                v0 = fmaxf(v0, 0.f); v1 = fmaxf(v1, 0.f);
                v2 = fmaxf(v2, 0.f); v3 = fmaxf(v3, 0.f);
            }
            *(float2*)(C + (size_t)row       * N + col) = make_float2(v0, v1);
            *(float2*)(C + (size_t)(row + 8) * N + col) = make_float2(v2, v3);
        }
    }
}

// ---------------------------------------------------------------------------
// rowops: per row r of 32768: un_pot = e·un_red_w + b, 1/||xe||, YE <- yn
// ---------------------------------------------------------------------------
__global__ void rowops_k(const float* __restrict__ E, const float* __restrict__ XE,
                         float* __restrict__ YE,
                         const float* __restrict__ unw, const float* __restrict__ unb,
                         float* __restrict__ unpot, float* __restrict__ invnx)
{
    __shared__ float red[3][8];
    __shared__ float fin[3];
    const int r = blockIdx.x, tid = threadIdx.x;
    const size_t base = (size_t)r * 768;

    const int i0 = tid, i1 = tid + 256, i2 = tid + 512;
    const float e0 = E[base + i0], e1 = E[base + i1], e2 = E[base + i2];
    float de = e0 * unw[i0] + e1 * unw[i1] + e2 * unw[i2];
    const float x0 = XE[base + i0], x1 = XE[base + i1], x2 = XE[base + i2];
    float sx = x0 * x0 + x1 * x1 + x2 * x2;
    const float y0 = YE[base + i0], y1 = YE[base + i1], y2 = YE[base + i2];
    float sy = y0 * y0 + y1 * y1 + y2 * y2;

    #pragma unroll
    for (int o = 16; o; o >>= 1) {
        de += __shfl_xor_sync(0xffffffffu, de, o);
        sx += __shfl_xor_sync(0xffffffffu, sx, o);
        sy += __shfl_xor_sync(0xffffffffu, sy, o);
    }
    if ((tid & 31) == 0) { int w = tid >> 5; red[0][w] = de; red[1][w] = sx; red[2][w] = sy; }
    __syncthreads();
    if (tid == 0) {
        float a = 0.f, b2 = 0.f, c = 0.f;
        #pragma unroll
        for (int i = 0; i < 8; i++) { a += red[0][i]; b2 += red[1][i]; c += red[2][i]; }
        fin[2] = c;
        unpot[r] = a + unb[0];
        invnx[r] = 1.f / fmaxf(sqrtf(b2), 1e-12f);
    }
    __syncthreads();
    const float inv_ny = 1.f / fmaxf(sqrtf(fin[2]), 1e-12f);
    YE[base + i0] = y0 * inv_ny;
    YE[base + i1] = y1 * inv_ny;
    YE[base + i2] = y2 * inv_ny;
}

// ybar[b,d] = mean_t yn[b,t,d]     grid (32, 6) x 128
__global__ void ybar_k(const float* __restrict__ YN, float* __restrict__ YB)
{
    const int b = blockIdx.x, col = blockIdx.y * 128 + threadIdx.x;
    const float* p = YN + (size_t)b * 1024 * 768 + col;
    float s = 0.f;
    #pragma unroll 8
    for (int tt = 0; tt < 1024; ++tt) s += p[(size_t)tt * 768];
    YB[b * 768 + col] = s * (1.0f / 1024.0f);
}

// scores[b,t] = rw0*un_pot + rw1*(xe·ybar)/||xe||
__global__ void scores_k(const float* __restrict__ XE, const float* __restrict__ YB,
                         const float* __restrict__ invnx, const float* __restrict__ unpot,
                         const float* __restrict__ redw, float* __restrict__ sc)
{
    __shared__ float red[8];
    const int r = blockIdx.x, tid = threadIdx.x;
    const int b = r >> 10;
    const size_t base = (size_t)r * 768;
    const float* yb = YB + b * 768;
    float d = XE[base + tid] * yb[tid]
            + XE[base + tid + 256] * yb[tid + 256]
            + XE[base + tid + 512] * yb[tid + 512];
    #pragma unroll
    for (int o = 16; o; o >>= 1) d += __shfl_xor_sync(0xffffffffu, d, o);
    if ((tid & 31) == 0) red[tid >> 5] = d;
    __syncthreads();
    if (tid == 0) {
        float D = 0.f;
        #pragma unroll
        for (int i = 0; i < 8; i++) D += red[i];
        const float pw = D * invnx[r];
        sc[r] = redw[0] * unpot[r] + redw[1] * pw;
    }
}

// softmax over T + weighted sum of U rows.  grid 32 x 256
__global__ void final_k(const float* __restrict__ U, const float* __restrict__ sc,
                        float* __restrict__ out)
{
    __shared__ float wsh[1024];
    __shared__ float red[8];
    __shared__ float finv;
    const int b = blockIdx.x, tid = threadIdx.x;

    float l0 = sc[b * 1024 + tid];
    float l1 = sc[b * 1024 + tid + 256];
    float l2 = sc[b * 1024 + tid + 512];
    float l3 = sc[b * 1024 + tid + 768];
    float mx = fmaxf(fmaxf(l0, l1), fmaxf(l2, l3));
    #pragma unroll
    for (int o = 16; o; o >>= 1) mx = fmaxf(mx, __shfl_xor_sync(0xffffffffu, mx, o));
    if ((tid & 31) == 0) red[tid >> 5] = mx;
    __syncthreads();
    if (tid == 0) {
        float M = red[0];
        #pragma unroll
        for (int i = 1; i < 8; i++) M = fmaxf(M, red[i]);
        finv = M;  // temporarily hold the max
    }
    __syncthreads();
    const float M = finv;
    __syncthreads();

    l0 = expf(l0 - M); l1 = expf(l1 - M); l2 = expf(l2 - M); l3 = expf(l3 - M);
    float s = l0 + l1 + l2 + l3;
    #pragma unroll
    for (int o = 16; o; o >>= 1) s += __shfl_xor_sync(0xffffffffu, s, o);
    if ((tid & 31) == 0) red[tid >> 5] = s;
    __syncthreads();
    if (tid == 0) {
        float S = 0.f;
        #pragma unroll
        for (int i = 0; i < 8; i++) S += red[i];
        finv = 1.f / S;
    }
    __syncthreads();
    const float inv = finv;
    wsh[tid]       = l0 * inv;
    wsh[tid + 256] = l1 * inv;
    wsh[tid + 512] = l2 * inv;
    wsh[tid + 768] = l3 * inv;
    __syncthreads();

    const float* Ub = U + (size_t)b * 1024 * 768;
    float a0 = 0.f, a1 = 0.f, a2 = 0.f;
    #pragma unroll 4
    for (int tt = 0; tt < 1024; ++tt) {
        const float wt = wsh[tt];
        const float* row = Ub + (size_t)tt * 768;
        a0 += wt * row[tid];
        a1 += wt * row[tid + 256];
        a2 += wt * row[tid + 512];
    }
    out[b * 768 + tid]       = a0;
    out[b * 768 + tid + 256] = a1;
    out[b * 768 + tid + 512] = a2;
}

// ---------------------------------------------------------------------------
extern "C" void kernel_launch(void* const* d_in, const int* in_sizes, int n_in,
                              void* d_out, int out_size)
{
    (void)in_sizes; (void)n_in; (void)out_size;
    const float* x       = (const float*)d_in[0];
    const float* fc1_w   = (const float*)d_in[1];
    const float* fc1_b   = (const float*)d_in[2];
    const float* fc2_w   = (const float*)d_in[3];
    const float* fc2_b   = (const float*)d_in[4];
    const float* un_emb_w= (const float*)d_in[5];
    const float* un_emb_b= (const float*)d_in[6];
    const float* un_red_w= (const float*)d_in[7];
    const float* un_red_b= (const float*)d_in[8];
    const float* pw_x_w  = (const float*)d_in[9];
    const float* pw_x_b  = (const float*)d_in[10];
    const float* pw_y_w  = (const float*)d_in[11];
    const float* pw_y_b  = (const float*)d_in[12];
    const float* red_w   = (const float*)d_in[13];
    float* out = (float*)d_out;

    float *H, *U, *E, *XE, *YE, *YB, *UP, *INX, *SC;
    cudaGetSymbolAddress((void**)&H,   g_H);
    cudaGetSymbolAddress((void**)&U,   g_U);
    cudaGetSymbolAddress((void**)&E,   g_E);
    cudaGetSymbolAddress((void**)&XE,  g_XE);
    cudaGetSymbolAddress((void**)&YE,  g_YE);
    cudaGetSymbolAddress((void**)&YB,  g_YB);
    cudaGetSymbolAddress((void**)&UP,  g_UP);
    cudaGetSymbolAddress((void**)&INX, g_INX);
    cudaGetSymbolAddress((void**)&SC,  g_SC);

    const int smem = 64 * 1024;
    cudaFuncSetAttribute(gemm_tf32<true>,  cudaFuncAttributeMaxDynamicSharedMemorySize, smem);
    cudaFuncSetAttribute(gemm_tf32<false>, cudaFuncAttributeMaxDynamicSharedMemorySize, smem);

    // 1. H = relu(x @ fc1_w^T + fc1_b)   [32768 x 1536], K=1536
    gemm_tf32<true><<<dim3(12, 256), 256, smem>>>(x, fc1_w, fc1_b, H, 1536, 1536);
    // 2. U = H @ fc2_w^T + fc2_b         [32768 x 768], K=1536
    gemm_tf32<false><<<dim3(6, 256), 256, smem>>>(H, fc2_w, fc2_b, U, 768, 1536);
    // 3-5. E / XE / YE                   [32768 x 768], K=768
    gemm_tf32<true><<<dim3(6, 256), 256, smem>>>(U, un_emb_w, un_emb_b, E, 768, 768);
    gemm_tf32<false><<<dim3(6, 256), 256, smem>>>(U, pw_x_w, pw_x_b, XE, 768, 768);
    gemm_tf32<false><<<dim3(6, 256), 256, smem>>>(U, pw_y_w, pw_y_b, YE, 768, 768);
    // 6. row reductions + in-place normalize YE -> yn
    rowops_k<<<Mn, 256>>>(E, XE, YE, un_red_w, un_red_b, UP, INX);
    // 7. ybar = mean_t yn
    ybar_k<<<dim3(Bn, 6), 128>>>(YE, YB);
    // 8. scores
    scores_k<<<Mn, 256>>>(XE, YB, INX, UP, red_w, SC);
    // 9. softmax + weighted sum
    final_k<<<Bn, 256>>>(U, SC, out);
}

// round 5
// speedup vs baseline: 1.3974x; 1.3940x over previous
#include <cuda_runtime.h>
#include <cstdint>
#include <cstddef>

namespace {
constexpr int Bn = 32, Tn = 1024, INn = 1536, Dn = 768;
constexpr int Mn = Bn * Tn;  // 32768
}

// Scratch (static __device__ globals: allocation-free rule)
__device__ __align__(256) float g_X [(size_t)Mn * INn];  // tf32-rounded x
__device__ __align__(256) float g_H [(size_t)Mn * INn];
__device__ __align__(256) float g_U [(size_t)Mn * Dn];
__device__ __align__(256) float g_E [(size_t)Mn * Dn];
__device__ __align__(256) float g_XE[(size_t)Mn * Dn];
__device__ __align__(256) float g_YE[(size_t)Mn * Dn];
__device__ __align__(256) float g_W1[(size_t)INn * INn];
__device__ __align__(256) float g_W2[(size_t)Dn * INn];
__device__ __align__(256) float g_W3[(size_t)Dn * Dn];
__device__ __align__(256) float g_W4[(size_t)Dn * Dn];
__device__ __align__(256) float g_W5[(size_t)Dn * Dn];
__device__ __align__(256) float g_YB[Bn * Dn];
__device__ __align__(256) float g_UP[Mn];
__device__ __align__(256) float g_INX[Mn];
__device__ __align__(256) float g_SC[Mn];

// ---------------------------------------------------------------------------
// helpers
// ---------------------------------------------------------------------------
__device__ __forceinline__ uint32_t smem_u32(const void* p) {
    uint32_t a;
    asm("{ .reg .u64 t; cvta.to.shared.u64 t, %1; cvt.u32.u64 %0, t; }" : "=r"(a) : "l"(p));
    return a;
}
__device__ __forceinline__ void cp16(float* s, const float* g) {
    uint32_t sa = (uint32_t)__cvta_generic_to_shared(s);
    asm volatile("cp.async.cg.shared.global [%0], [%1], 16;\n" :: "r"(sa), "l"(g));
}
__device__ __forceinline__ void cp_commit() { asm volatile("cp.async.commit_group;\n"); }
template <int NW> __device__ __forceinline__ void cp_wait() {
    asm volatile("cp.async.wait_group %0;\n" :: "n"(NW));
}
__device__ __forceinline__ uint32_t f2tf(float x) {
    uint32_t r;
    asm("cvt.rna.tf32.f32 %0, %1;\n" : "=r"(r) : "f"(x));
    return r;
}
__device__ __forceinline__ void mma8(float* c, const uint32_t* a, const uint32_t* b) {
    asm volatile(
        "mma.sync.aligned.m16n8k8.row.col.f32.tf32.tf32.f32 "
        "{%0,%1,%2,%3}, {%4,%5,%6,%7}, {%8,%9}, {%0,%1,%2,%3};\n"
        : "+f"(c[0]), "+f"(c[1]), "+f"(c[2]), "+f"(c[3])
        : "r"(a[0]), "r"(a[1]), "r"(a[2]), "r"(a[3]), "r"(b[0]), "r"(b[1]));
}
// ldmatrix on 32-bit data: an 8x4-f32 block viewed as 8x8-b16. x4 yields the
// full m16n8k8 tf32 A fragment; x2 yields the B fragment.
__device__ __forceinline__ void ldsm4(uint32_t* r, uint32_t addr) {
    asm volatile("ldmatrix.sync.aligned.m8n8.x4.shared.b16 {%0,%1,%2,%3}, [%4];"
                 : "=r"(r[0]), "=r"(r[1]), "=r"(r[2]), "=r"(r[3]) : "r"(addr));
}
__device__ __forceinline__ void ldsm2(uint32_t* r, uint32_t addr) {
    asm volatile("ldmatrix.sync.aligned.m8n8.x2.shared.b16 {%0,%1}, [%2];"
                 : "=r"(r[0]), "=r"(r[1]) : "r"(addr));
}

__global__ void round_k(const float4* __restrict__ src, float4* __restrict__ dst, int n4)
{
    int i = blockIdx.x * 256 + threadIdx.x;
    if (i >= n4) return;
    float4 v = src[i];
    v.x = __uint_as_float(f2tf(v.x)); v.y = __uint_as_float(f2tf(v.y));
    v.z = __uint_as_float(f2tf(v.z)); v.w = __uint_as_float(f2tf(v.w));
    dst[i] = v;
}

// ---------------------------------------------------------------------------
// GEMM: C[M,N] = A[M,K] @ W[N,K]^T + bias[N], optional relu, output tf32-rounded.
// Inputs MUST already be tf32-valued (pre-rounded): no cvt in the hot loop.
// CTA 128x128x32, warps 2(m)x4(n), m16n8k8 tf32, ldmatrix fragment loads,
// double-buffered cp.async. M%128==0, N%128==0, K%32==0.
// ---------------------------------------------------------------------------
template <bool RELU>
__global__ __launch_bounds__(256, 2) void gemm_tf32(
    const float* __restrict__ A, const float* __restrict__ W,
    const float* __restrict__ bias, float* __restrict__ C,
    int N, int K)
{
    extern __shared__ float smem[];  // [0,8192): A x2 stages, [8192,16384): B x2
    const int tid  = threadIdx.x;
    const int lane = tid & 31, wrp = tid >> 5;
    const int wm = wrp >> 2, wn = wrp & 3;
    const int m0 = blockIdx.y * 128, n0 = blockIdx.x * 128;

    // loader mapping (same swizzle as reader): row r, col-group c4 at
    // float offset r*32 + ((c4 ^ (r&7))<<2)
    const int c4 = tid & 7, rb = tid >> 3;
    const int soff = rb * 32 + ((c4 ^ (rb & 7)) << 2);
    const float* gA = A + (size_t)(m0 + rb) * K + c4 * 4;
    const float* gW = W + (size_t)(n0 + rb) * K + c4 * 4;

    // ldmatrix per-lane geometry
    const uint32_t smb = smem_u32(smem);
    const int s7 = lane & 7;
    const int half = (lane >> 3) & 1;        // A: matrices 1,3 take rows +8
    const int koffA = lane >> 4;             // A: matrices 2,3 take col4 +1
    const int koffB = (lane >> 3) & 1;       // B: matrix 1 takes col4 +1
    uint32_t rowA[4], rowB[4];
    #pragma unroll
    for (int mf = 0; mf < 4; mf++)
        rowA[mf] = (uint32_t)(wm * 64 + mf * 16 + half * 8 + s7) * 128u;
    #pragma unroll
    for (int nf = 0; nf < 4; nf++)
        rowB[nf] = (uint32_t)(wn * 32 + nf * 8 + s7) * 128u;

    float acc[4][4][4];
    #pragma unroll
    for (int i = 0; i < 4; i++)
        #pragma unroll
        for (int j = 0; j < 4; j++)
            #pragma unroll
            for (int q = 0; q < 4; q++) acc[i][j][q] = 0.f;

    const int kiters = K >> 5;

    #pragma unroll
    for (int p = 0; p < 4; p++) {
        cp16(&smem[soff + p * 1024],        gA + (size_t)p * 32 * K);
        cp16(&smem[8192 + soff + p * 1024], gW + (size_t)p * 32 * K);
    }
    cp_commit();

    for (int it = 0; it < kiters; ++it) {
        const int st = it & 1;
        if (it + 1 < kiters) {
            const int k0  = (it + 1) << 5;
            const int stn = (it + 1) & 1;
            #pragma unroll
            for (int p = 0; p < 4; p++) {
                cp16(&smem[stn * 4096 + soff + p * 1024],        gA + k0 + (size_t)p * 32 * K);
                cp16(&smem[8192 + stn * 4096 + soff + p * 1024], gW + k0 + (size_t)p * 32 * K);
            }
            cp_commit();
            cp_wait<1>();
        } else {
            cp_wait<0>();
        }
        __syncthreads();

        const uint32_t stA = smb + (uint32_t)st * 16384u;
        const uint32_t stB = smb + 32768u + (uint32_t)st * 16384u;

        #pragma unroll
        for (int kk4 = 0; kk4 < 8; kk4 += 2) {
            const uint32_t colA = (uint32_t)(((kk4 + koffA) ^ s7) << 4);
            const uint32_t colB = (uint32_t)(((kk4 + koffB) ^ s7) << 4);
            uint32_t af[4][4], bf[4][2];
            #pragma unroll
            for (int mf = 0; mf < 4; mf++) ldsm4(af[mf], stA + rowA[mf] + colA);
            #pragma unroll
            for (int nf = 0; nf < 4; nf++) ldsm2(bf[nf], stB + rowB[nf] + colB);
            #pragma unroll
            for (int mf = 0; mf < 4; mf++)
                #pragma unroll
                for (int nf = 0; nf < 4; nf++)
                    mma8(acc[mf][nf], af[mf], bf[nf]);
        }
        __syncthreads();
    }

    // epilogue: bias (+relu), tf32-round, float2 stores
    const int g = lane >> 2, t = lane & 3;
    #pragma unroll
    for (int mf = 0; mf < 4; mf++) {
        const int row = m0 + wm * 64 + mf * 16 + g;
        #pragma unroll
        for (int nf = 0; nf < 4; nf++) {
            const int col = n0 + wn * 32 + nf * 8 + 2 * t;
            const float b0 = bias[col], b1 = bias[col + 1];
            float v0 = acc[mf][nf][0] + b0;
            float v1 = acc[mf][nf][1] + b1;
            float v2 = acc[mf][nf][2] + b0;
            float v3 = acc[mf][nf][3] + b1;
            if (RELU) {
                v0 = fmaxf(v0, 0.f); v1 = fmaxf(v1, 0.f);
                v2 = fmaxf(v2, 0.f); v3 = fmaxf(v3, 0.f);
            }
            v0 = __uint_as_float(f2tf(v0)); v1 = __uint_as_float(f2tf(v1));
            v2 = __uint_as_float(f2tf(v2)); v3 = __uint_as_float(f2tf(v3));
            *(float2*)(C + (size_t)row       * N + col) = make_float2(v0, v1);
            *(float2*)(C + (size_t)(row + 8) * N + col) = make_float2(v2, v3);
        }
    }
}

// --------------------------- tail kernels ----------------------------------
__global__ void rowops_k(const float* __restrict__ E, const float* __restrict__ XE,
                         float* __restrict__ YE,
                         const float* __restrict__ unw, const float* __restrict__ unb,
                         float* __restrict__ unpot, float* __restrict__ invnx)
{
    __shared__ float red[3][8];
    __shared__ float fin;
    const int r = blockIdx.x, tid = threadIdx.x;
    const size_t base = (size_t)r * 768;
    const int i0 = tid, i1 = tid + 256, i2 = tid + 512;
    const float e0 = E[base + i0], e1 = E[base + i1], e2 = E[base + i2];
    float de = e0 * unw[i0] + e1 * unw[i1] + e2 * unw[i2];
    const float x0 = XE[base + i0], x1 = XE[base + i1], x2 = XE[base + i2];
    float sx = x0 * x0 + x1 * x1 + x2 * x2;
    const float y0 = YE[base + i0], y1 = YE[base + i1], y2 = YE[base + i2];
    float sy = y0 * y0 + y1 * y1 + y2 * y2;
    #pragma unroll
    for (int o = 16; o; o >>= 1) {
        de += __shfl_xor_sync(0xffffffffu, de, o);
        sx += __shfl_xor_sync(0xffffffffu, sx, o);
        sy += __shfl_xor_sync(0xffffffffu, sy, o);
    }
    if ((tid & 31) == 0) { int w = tid >> 5; red[0][w] = de; red[1][w] = sx; red[2][w] = sy; }
    __syncthreads();
    if (tid == 0) {
        float a = 0.f, b2 = 0.f, c = 0.f;
        #pragma unroll
        for (int i = 0; i < 8; i++) { a += red[0][i]; b2 += red[1][i]; c += red[2][i]; }
        fin = c;
        unpot[r] = a + unb[0];
        invnx[r] = 1.f / fmaxf(sqrtf(b2), 1e-12f);
    }
    __syncthreads();
    const float inv_ny = 1.f / fmaxf(sqrtf(fin), 1e-12f);
    YE[base + i0] = y0 * inv_ny;
    YE[base + i1] = y1 * inv_ny;
    YE[base + i2] = y2 * inv_ny;
}

__global__ void ybar_k(const float* __restrict__ YN, float* __restrict__ YB)
{
    const int b = blockIdx.x, col = blockIdx.y * 128 + threadIdx.x;
    const float* p = YN + (size_t)b * 1024 * 768 + col;
    float s = 0.f;
    #pragma unroll 8
    for (int tt = 0; tt < 1024; ++tt) s += p[(size_t)tt * 768];
    YB[b * 768 + col] = s * (1.0f / 1024.0f);
}

__global__ void scores_k(const float* __restrict__ XE, const float* __restrict__ YB,
                         const float* __restrict__ invnx, const float* __restrict__ unpot,
                         const float* __restrict__ redw, float* __restrict__ sc)
{
    __shared__ float red[8];
    const int r = blockIdx.x, tid = threadIdx.x;
    const int b = r >> 10;
    const size_t base = (size_t)r * 768;
    const float* yb = YB + b * 768;
    float d = XE[base + tid] * yb[tid]
            + XE[base + tid + 256] * yb[tid + 256]
            + XE[base + tid + 512] * yb[tid + 512];
    #pragma unroll
    for (int o = 16; o; o >>= 1) d += __shfl_xor_sync(0xffffffffu, d, o);
    if ((tid & 31) == 0) red[tid >> 5] = d;
    __syncthreads();
    if (tid == 0) {
        float D = 0.f;
        #pragma unroll
        for (int i = 0; i < 8; i++) D += red[i];
        sc[r] = redw[0] * unpot[r] + redw[1] * (D * invnx[r]);
    }
}

__global__ void final_k(const float* __restrict__ U, const float* __restrict__ sc,
                        float* __restrict__ out)
{
    __shared__ float wsh[1024];
    __shared__ float red[8];
    __shared__ float finv;
    const int b = blockIdx.x, tid = threadIdx.x;
    float l0 = sc[b * 1024 + tid];
    float l1 = sc[b * 1024 + tid + 256];
    float l2 = sc[b * 1024 + tid + 512];
    float l3 = sc[b * 1024 + tid + 768];
    float mx = fmaxf(fmaxf(l0, l1), fmaxf(l2, l3));
    #pragma unroll
    for (int o = 16; o; o >>= 1) mx = fmaxf(mx, __shfl_xor_sync(0xffffffffu, mx, o));
    if ((tid & 31) == 0) red[tid >> 5] = mx;
    __syncthreads();
    if (tid == 0) {
        float M = red[0];
        #pragma unroll
        for (int i = 1; i < 8; i++) M = fmaxf(M, red[i]);
        finv = M;
    }
    __syncthreads();
    const float M = finv;
    __syncthreads();
    l0 = expf(l0 - M); l1 = expf(l1 - M); l2 = expf(l2 - M); l3 = expf(l3 - M);
    float s = l0 + l1 + l2 + l3;
    #pragma unroll
    for (int o = 16; o; o >>= 1) s += __shfl_xor_sync(0xffffffffu, s, o);
    if ((tid & 31) == 0) red[tid >> 5] = s;
    __syncthreads();
    if (tid == 0) {
        float S = 0.f;
        #pragma unroll
        for (int i = 0; i < 8; i++) S += red[i];
        finv = 1.f / S;
    }
    __syncthreads();
    const float inv = finv;
    wsh[tid]       = l0 * inv;
    wsh[tid + 256] = l1 * inv;
    wsh[tid + 512] = l2 * inv;
    wsh[tid + 768] = l3 * inv;
    __syncthreads();
    const float* Ub = U + (size_t)b * 1024 * 768;
    float a0 = 0.f, a1 = 0.f, a2 = 0.f;
    #pragma unroll 4
    for (int tt = 0; tt < 1024; ++tt) {
        const float wt = wsh[tt];
        const float* row = Ub + (size_t)tt * 768;
        a0 += wt * row[tid];
        a1 += wt * row[tid + 256];
        a2 += wt * row[tid + 512];
    }
    out[b * 768 + tid]       = a0;
    out[b * 768 + tid + 256] = a1;
    out[b * 768 + tid + 512] = a2;
}

// ---------------------------------------------------------------------------
extern "C" void kernel_launch(void* const* d_in, const int* in_sizes, int n_in,
                              void* d_out, int out_size)
{
    (void)in_sizes; (void)n_in; (void)out_size;
    const float* x        = (const float*)d_in[0];
    const float* fc1_b    = (const float*)d_in[2];
    const float* fc2_b    = (const float*)d_in[4];
    const float* un_emb_b = (const float*)d_in[6];
    const float* un_red_w = (const float*)d_in[7];
    const float* un_red_b = (const float*)d_in[8];
    const float* pw_x_b   = (const float*)d_in[10];
    const float* pw_y_b   = (const float*)d_in[12];
    const float* red_w    = (const float*)d_in[13];
    float* out = (float*)d_out;

    float *X, *H, *U, *E, *XE, *YE, *W1, *W2, *W3, *W4, *W5, *YB, *UP, *INX, *SC;
    cudaGetSymbolAddress((void**)&X,   g_X);
    cudaGetSymbolAddress((void**)&H,   g_H);
    cudaGetSymbolAddress((void**)&U,   g_U);
    cudaGetSymbolAddress((void**)&E,   g_E);
    cudaGetSymbolAddress((void**)&XE,  g_XE);
    cudaGetSymbolAddress((void**)&YE,  g_YE);
    cudaGetSymbolAddress((void**)&W1,  g_W1);
    cudaGetSymbolAddress((void**)&W2,  g_W2);
    cudaGetSymbolAddress((void**)&W3,  g_W3);
    cudaGetSymbolAddress((void**)&W4,  g_W4);
    cudaGetSymbolAddress((void**)&W5,  g_W5);
    cudaGetSymbolAddress((void**)&YB,  g_YB);
    cudaGetSymbolAddress((void**)&UP,  g_UP);
    cudaGetSymbolAddress((void**)&INX, g_INX);
    cudaGetSymbolAddress((void**)&SC,  g_SC);

    const int smem = 64 * 1024;
    cudaFuncSetAttribute(gemm_tf32<true>,  cudaFuncAttributeMaxDynamicSharedMemorySize, smem);
    cudaFuncSetAttribute(gemm_tf32<false>, cudaFuncAttributeMaxDynamicSharedMemorySize, smem);

    // pre-round all GEMM operands to tf32 (rna)
    round_k<<<Mn * INn / 4 / 256, 256>>>((const float4*)x, (float4*)X, Mn * INn / 4);
    round_k<<<INn * INn / 4 / 256, 256>>>((const float4*)d_in[1], (float4*)W1, INn * INn / 4);
    round_k<<<Dn * INn / 4 / 256, 256>>>((const float4*)d_in[3], (float4*)W2, Dn * INn / 4);
    round_k<<<Dn * Dn / 4 / 256, 256>>>((const float4*)d_in[5], (float4*)W3, Dn * Dn / 4);
    round_k<<<Dn * Dn / 4 / 256, 256>>>((const float4*)d_in[9], (float4*)W4, Dn * Dn / 4);
    round_k<<<Dn * Dn / 4 / 256, 256>>>((const float4*)d_in[11], (float4*)W5, Dn * Dn / 4);

    // 1. H = round(relu(X @ W1^T + b))   [32768 x 1536], K=1536
    gemm_tf32<true><<<dim3(12, 256), 256, smem>>>(X, W1, fc1_b, H, 1536, 1536);
    // 2. U = round(H @ W2^T + b)         [32768 x 768], K=1536
    gemm_tf32<false><<<dim3(6, 256), 256, smem>>>(H, W2, fc2_b, U, 768, 1536);
    // 3-5. E / XE / YE                   [32768 x 768], K=768
    gemm_tf32<true><<<dim3(6, 256), 256, smem>>>(U, W3, un_emb_b, E, 768, 768);
    gemm_tf32<false><<<dim3(6, 256), 256, smem>>>(U, W4, pw_x_b, XE, 768, 768);
    gemm_tf32<false><<<dim3(6, 256), 256, smem>>>(U, W5, pw_y_b, YE, 768, 768);
    // 6-9. reductions, scores, softmax-weighted sum
    rowops_k<<<Mn, 256>>>(E, XE, YE, un_red_w, un_red_b, UP, INX);
    ybar_k<<<dim3(Bn, 6), 128>>>(YE, YB);
    scores_k<<<Mn, 256>>>(XE, YB, INX, UP, red_w, SC);
    final_k<<<Bn, 256>>>(U, SC, out);
}